// round 12
// baseline (speedup 1.0000x reference)
#include <cuda_runtime.h>
#include <cuda_fp16.h>
#include <math.h>

// ---------------- problem constants ----------------
#define NQ      32768      // BATCH*2 query rows
#define D       128
#define GW      512        // packed gate width, INTERLEAVED: cg = 4*j + gate, j<128
#define FEW     5
#define SSTA    264        // A smem stride (halfs), K=256 + pad (conflict-free)
#define SSTB    136        // B smem stride (halfs), K=128 tile (conflict-free)

// k_gf smem layout (bytes)
#define OFF_BS    67584                 // As: 128*264*2
#define OFF_HLS   102400                // Bs: 128*136*2
#define OFF_SAT   110592                // hl_s: 128*32*2
#define OFF_SS2   113152                // sAt: 128*5*4
#define OFF_BIAS  114432                // sS2h: 5*128*2
#define SMEM_GF   114944                // sBias: 128*4

// ---------------- scratch (static device arrays; no allocation) ----------------
__device__ float  d_SG[FEW * D];                 // support_g (5 x 128)
__device__ float  d_S2[FEW * GW];                // SG @ W2.T, interleaved cols
__device__ float  d_MS[D];                       // mean_support
__device__ float  d_q   [(size_t)NQ * D];        // gathered query embeddings (fp32)
__device__ __half d_qhl [(size_t)NQ * 256];      // cols 0-127: q16 ; 128-255: hl16 (init -q)
__device__ float  d_c   [(size_t)256 * 256 * 128]; // cell state, thread-private layout
__device__ float  d_attn[(size_t)NQ * 8];        // attention weights (5, padded 8)
__device__ __half d_Wbig[GW * 256];              // [Wih+W1 | W1] interleaved 512x256 (fp16)
__device__ float  d_bsum[GW];                    // interleaved b_ih + b_hh

__device__ __forceinline__ float sigf(float x) {
    return __fdividef(1.0f, 1.0f + __expf(-x));
}
__device__ __forceinline__ float tanhfast(float x) {
    return __fdividef(2.0f, 1.0f + __expf(-2.0f * x)) - 1.0f;
}

__device__ __forceinline__ void mma_f16(float* c, const unsigned* a, unsigned b0, unsigned b1) {
    asm volatile(
        "mma.sync.aligned.m16n8k16.row.col.f32.f16.f16.f32 "
        "{%0,%1,%2,%3}, {%4,%5,%6,%7}, {%8,%9}, {%0,%1,%2,%3};"
        : "+f"(c[0]), "+f"(c[1]), "+f"(c[2]), "+f"(c[3])
        : "r"(a[0]), "r"(a[1]), "r"(a[2]), "r"(a[3]), "r"(b0), "r"(b1));
}

// ---------------- prep: interleaved fp16 Wbig = [Wih + W1 | W1] / bsum ----------------
// interleaved row pr: j = pr>>2, gate = pr&3 ; original gate row = gate*256 + j
__global__ void k_wsum(const float* __restrict__ Wih, const float* __restrict__ Whh,
                       const float* __restrict__ bih, const float* __restrict__ bhh) {
    int idx = blockIdx.x * 256 + threadIdx.x;           // 512*256 = 131072
    int pr = idx >> 8, k = idx & 255;
    int orig = ((pr & 3) << 8) + (pr >> 2);             // gate*256 + j
    float val;
    if (k < 128) val = Wih[(size_t)orig * 128 + k] + Whh[(size_t)orig * 256 + k];
    else         val = Whh[(size_t)orig * 256 + (k - 128)];
    d_Wbig[idx] = __float2half_rn(val);
    if (idx < GW) {
        int o2 = ((idx & 3) << 8) + (idx >> 2);
        d_bsum[idx] = bih[o2] + bhh[o2];
    }
}

// ---------------- support path: GCN (linear!) + MLP + LayerNorm ----------------
__global__ void k_support(const int* __restrict__ sp, const float* __restrict__ emb,
                          const float* __restrict__ gW, const float* __restrict__ gb,
                          const float* __restrict__ p1W, const float* __restrict__ p1b,
                          const float* __restrict__ p2W, const float* __restrict__ p2b,
                          const float* __restrict__ lng, const float* __restrict__ lnb) {
    __shared__ float cs[256], s[128], h1[256], x[128], stat[2];
    int f = blockIdx.x, t = threadIdx.x;
    int side = t >> 7, col = t & 127;
    const int* pf = sp + f * 400;
    float acc = 0.f;
    #pragma unroll 4
    for (int n = 0; n < 200; n++) {
        int idx = pf[n * 2 + side];
        acc += emb[(size_t)idx * 128 + col];
    }
    cs[t] = acc;
    __syncthreads();
    if (t < 128) {
        float a = 200.f * gb[t];
        #pragma unroll 4
        for (int k = 0; k < 256; k++) a = fmaf(cs[k], gW[t * 256 + k], a);
        s[t] = tanhf(a * 0.2f);
    }
    __syncthreads();
    {
        float a = p1b[t];
        #pragma unroll 4
        for (int j = 0; j < 128; j++) a = fmaf(s[j], p1W[t * 128 + j], a);
        h1[t] = fmaxf(a, 0.f);
    }
    __syncthreads();
    if (t < 128) {
        float a = p2b[t];
        #pragma unroll 4
        for (int k = 0; k < 256; k++) a = fmaf(h1[k], p2W[t * 256 + k], a);
        x[t] = a + s[t];
    }
    __syncthreads();
    if (t == 0) {
        float mu = 0.f;
        for (int j = 0; j < 128; j++) mu += x[j];
        mu *= (1.f / 128.f);
        float v = 0.f;
        for (int j = 0; j < 128; j++) { float dd = x[j] - mu; v += dd * dd; }
        v *= (1.f / 128.f);
        stat[0] = mu; stat[1] = rsqrtf(v + 1e-5f);
    }
    __syncthreads();
    if (t < 128) d_SG[f * 128 + t] = lng[t] * (x[t] - stat[0]) * stat[1] + lnb[t];
}

// ---------------- S2 (interleaved 512 cols) + mean_support ----------------
__global__ void k_s2mean(const float* __restrict__ Whh) {
    __shared__ float sg[128];
    int b = blockIdx.x, t = threadIdx.x;
    if (b < 20) {
        int f = b >> 2, gbk = b & 3;
        sg[t] = d_SG[f * 128 + t];
        __syncthreads();
        int pc = gbk * 128 + t;
        int orig = ((pc & 3) << 8) + (pc >> 2);
        float a = 0.f;
        #pragma unroll 4
        for (int j = 0; j < 128; j++) a = fmaf(sg[j], Whh[(size_t)orig * 256 + 128 + j], a);
        d_S2[f * GW + pc] = a;
    } else {
        float a = 0.f;
        #pragma unroll
        for (int f = 0; f < FEW; f++) a += d_SG[f * 128 + t];
        d_MS[t] = a * 0.2f;
    }
}

// ---------------- gather: q fp32, qhl = [q16 | -q16] (step-0 trick) ----------------
__global__ void k_gather(const int* __restrict__ qp, const float* __restrict__ emb) {
    int row = blockIdx.x * 8 + (threadIdx.x >> 5);
    int lane = threadIdx.x & 31;
    int idx = qp[row];
    float4 v = *(const float4*)(emb + (size_t)idx * 128 + lane * 4);
    *(float4*)(d_q + (size_t)row * 128 + lane * 4) = v;
    __half* qr = d_qhl + (size_t)row * 256;
    *(__half2*)(qr + lane * 4)           = __floats2half2_rn(v.x, v.y);
    *(__half2*)(qr + lane * 4 + 2)       = __floats2half2_rn(v.z, v.w);
    *(__half2*)(qr + 128 + lane * 4)     = __floats2half2_rn(-v.x, -v.y);
    *(__half2*)(qr + 128 + lane * 4 + 2) = __floats2half2_rn(-v.z, -v.w);
}

// ---------------- fused step: GEMM + register/shuffle LSTM, no gates tensor ----------------
// gates = [q|hl] @ [Wc|W1].T + b (+ attn@S2), interleaved cols. Tile nn covers cells
// j in [nn*32, nn*32+32): even-tg lanes hold (i,f), odd-tg (g,o) of the SAME cell;
// partner = lane^1. c uses a thread-private layout (same thread each step).
__global__ void __launch_bounds__(256, 2) k_gf(int first, int hasattn, int last) {
    extern __shared__ char smraw[];
    __half* As   = (__half*)smraw;                       // 128 x 264
    __half* Bs   = (__half*)(smraw + OFF_BS);            // 128 x 136
    __half* hl_s = (__half*)(smraw + OFF_HLS);           // 128 x 32
    float*  sAt  = (float*)(smraw + OFF_SAT);            // 128 x 5
    __half* sS2h = (__half*)(smraw + OFF_SS2);           // 5 x 128 (per tile)
    float*  sBias= (float*)(smraw + OFF_BIAS);           // 128 (per tile)

    int by = blockIdx.x;
    int tid = threadIdx.x, lane = tid & 31, warp = tid >> 5;
    int g = lane >> 2, tg = lane & 3;
    int wm = warp >> 2, wn = warp & 3;                   // 2(M) x 4(N); warp tile 64 x 32
    bool evenp = (tg & 1) == 0;

    // A tile: 128 rows x 256 halfs (q | hl)
    const __half* Ag = d_qhl + (size_t)by * 128 * 256;
    #pragma unroll
    for (int it = 0; it < 16; it++) {
        int i = tid + it * 256; int r = i >> 5, c8 = (i & 31) << 3;
        *(uint4*)(As + r * SSTA + c8) = *(const uint4*)(Ag + r * 256 + c8);
    }
    if (hasattn) {
        for (int i = tid; i < 128 * FEW; i += 256) {
            int r = i / FEW, f = i - r * FEW;
            sAt[i] = d_attn[(size_t)(by * 128 + r) * 8 + f];
        }
    }
    size_t cbase = ((size_t)by * 256 + tid) * 128;

    for (int nn = 0; nn < 4; nn++) {
        float acc[4][4][4];
        #pragma unroll
        for (int mi = 0; mi < 4; mi++)
            #pragma unroll
            for (int ni = 0; ni < 4; ni++)
                #pragma unroll
                for (int r = 0; r < 4; r++) acc[mi][ni][r] = 0.f;

        #pragma unroll
        for (int kh = 0; kh < 2; kh++) {
            __syncthreads();                 // Bs free; hl_s flush done; As/sAt ready
            const __half* Bg = d_Wbig + (size_t)(nn * 128) * 256 + kh * 128;
            #pragma unroll
            for (int it = 0; it < 8; it++) {
                int i = tid + it * 256; int r = i >> 4, c8 = (i & 15) << 3;
                *(uint4*)(Bs + r * SSTB + c8) = *(const uint4*)(Bg + r * 256 + c8);
            }
            if (kh == 0) {
                if (hasattn)
                    for (int i = tid; i < FEW * 128; i += 256)
                        sS2h[i] = __float2half_rn(d_S2[(i >> 7) * GW + nn * 128 + (i & 127)]);
                if (tid < 128) sBias[tid] = d_bsum[nn * 128 + tid];
            }
            __syncthreads();

            #pragma unroll
            for (int kk = 0; kk < 8; kk++) {
                int ca = kh * 128 + kk * 16 + 2 * tg;
                int cb = kk * 16 + 2 * tg;
                unsigned a[4][4];
                #pragma unroll
                for (int mi = 0; mi < 4; mi++) {
                    const __half* p = As + (wm * 64 + mi * 16 + g) * SSTA + ca;
                    a[mi][0] = *(const unsigned*)(p);
                    a[mi][1] = *(const unsigned*)(p + 8 * SSTA);
                    a[mi][2] = *(const unsigned*)(p + 8);
                    a[mi][3] = *(const unsigned*)(p + 8 * SSTA + 8);
                }
                #pragma unroll
                for (int ni = 0; ni < 4; ni++) {
                    const __half* p = Bs + (wn * 32 + ni * 8 + g) * SSTB + cb;
                    unsigned b0 = *(const unsigned*)(p);
                    unsigned b1 = *(const unsigned*)(p + 8);
                    #pragma unroll
                    for (int mi = 0; mi < 4; mi++)
                        mma_f16(acc[mi][ni], a[mi], b0, b1);
                }
            }
        }

        // ---- fused LSTM epilogue for cells j in [nn*32, nn*32+32) ----
        #pragma unroll
        for (int mi = 0; mi < 4; mi++) {
            #pragma unroll
            for (int ni = 0; ni < 4; ni++) {
                #pragma unroll
                for (int rr = 0; rr < 2; rr++) {
                    int rl = wm * 64 + mi * 16 + g + rr * 8;
                    int c2 = wn * 32 + ni * 8 + 2 * tg;
                    float x0 = acc[mi][ni][rr * 2 + 0] + sBias[c2];
                    float x1 = acc[mi][ni][rr * 2 + 1] + sBias[c2 + 1];
                    if (hasattn) {
                        #pragma unroll
                        for (int f = 0; f < FEW; f++) {
                            float av = sAt[rl * FEW + f];
                            x0 = fmaf(av, __half2float(sS2h[f * 128 + c2]), x0);
                            x1 = fmaf(av, __half2float(sS2h[f * 128 + c2 + 1]), x1);
                        }
                    }
                    // even lanes: (x0,x1)=(i_pre,f_pre) ; odd: (g_pre,o_pre)
                    float va = evenp ? sigf(x0) : tanhfast(x0);
                    float vb = sigf(x1);
                    float tgn = __shfl_xor_sync(0xffffffffu, va, 1); // even <- tanh(g)
                    float cn = 0.f;
                    if (evenp) {
                        int p = mi * 8 + ni * 2 + rr;
                        float cp = first ? 0.f : d_c[cbase + nn * 32 + p];
                        cn = fmaf(vb, cp, va * tgn);
                        if (!last) d_c[cbase + nn * 32 + p] = cn;
                    }
                    float cx = __shfl_xor_sync(0xffffffffu, cn, 1);  // odd <- c_new
                    if (!evenp) {
                        float hl = vb * tanhfast(cx);
                        int jl = c2 >> 2;                            // 0..31
                        hl_s[rl * 32 + jl] = __float2half_rn(hl);
                    }
                }
            }
        }
        __syncthreads();                     // hl_s complete
        {
            int r = tid >> 1, ch = tid & 1;
            const uint4* src = (const uint4*)(hl_s + r * 32) + ch;
            uint4* dst = (uint4*)(d_qhl + (size_t)(by * 128 + r) * 256 + 128 + nn * 32) + ch;
            uint4 v0 = src[0];
            uint4 v1 = src[2];
            dst[0] = v0;
            dst[2] = v1;
        }
    }
}

// ---------------- attention logits + softmax (between steps) ----------------
__global__ void __launch_bounds__(256) k_attn() {
    __shared__ float sSg[FEW * 128];
    for (int i = threadIdx.x; i < FEW * 128; i += 256) sSg[i] = d_SG[i];
    __syncthreads();
    int row = blockIdx.x * 8 + (threadIdx.x >> 5);
    int lane = threadIdx.x & 31;
    const __half* qr = d_qhl + (size_t)row * 256;
    float part[FEW] = {0.f, 0.f, 0.f, 0.f, 0.f};
    #pragma unroll
    for (int k = 0; k < 4; k++) {
        int j = lane + 32 * k;
        float hq = __half2float(qr[j]) + __half2float(qr[128 + j]);
        #pragma unroll
        for (int f = 0; f < FEW; f++) part[f] = fmaf(hq, sSg[f * 128 + j], part[f]);
    }
    #pragma unroll
    for (int o = 16; o; o >>= 1)
        #pragma unroll
        for (int f = 0; f < FEW; f++) part[f] += __shfl_xor_sync(0xffffffffu, part[f], o);
    if (lane == 0) {
        float m = part[0];
        #pragma unroll
        for (int f = 1; f < FEW; f++) m = fmaxf(m, part[f]);
        float e[FEW], ss = 0.f;
        #pragma unroll
        for (int f = 0; f < FEW; f++) { e[f] = __expf(part[f] - m); ss += e[f]; }
        float inv = __fdividef(1.f, ss);
        #pragma unroll
        for (int f = 0; f < FEW; f++) d_attn[(size_t)row * 8 + f] = e[f] * inv;
    }
}

// ---------------- final: out[b] = mean(hq[2b], hq[2b+1]) . mean_support ----------------
__global__ void k_final(float* __restrict__ out) {
    __shared__ float ms[128];
    int t = threadIdx.x;
    if (t < 128) ms[t] = d_MS[t];
    __syncthreads();
    int b = blockIdx.x * 8 + (t >> 5);
    int lane = t & 31;
    const float*  q0 = d_q + (size_t)b * 256;
    const __half* hb = d_qhl + (size_t)b * 512;
    int j = lane * 4;
    float4 qa = *(const float4*)(q0 + j);
    float4 qb = *(const float4*)(q0 + 128 + j);
    __half2 h0a = *(const __half2*)(hb + 128 + j);
    __half2 h0b = *(const __half2*)(hb + 128 + j + 2);
    __half2 h1a = *(const __half2*)(hb + 384 + j);
    __half2 h1b = *(const __half2*)(hb + 384 + j + 2);
    float2 f0a = __half22float2(h0a), f0b = __half22float2(h0b);
    float2 f1a = __half22float2(h1a), f1b = __half22float2(h1b);
    float4 m4 = *(const float4*)(ms + j);
    float p = 0.5f * ((qa.x + f0a.x + qb.x + f1a.x) * m4.x +
                      (qa.y + f0a.y + qb.y + f1a.y) * m4.y +
                      (qa.z + f0b.x + qb.z + f1b.x) * m4.z +
                      (qa.w + f0b.y + qb.w + f1b.y) * m4.w);
    #pragma unroll
    for (int o = 16; o; o >>= 1) p += __shfl_xor_sync(0xffffffffu, p, o);
    if (lane == 0) out[b] = p;
}

// ---------------- launcher ----------------
extern "C" void kernel_launch(void* const* d_in, const int* in_sizes, int n_in,
                              void* d_out, int out_size) {
    const int*   qp  = (const int*)d_in[0];
    const int*   sp  = (const int*)d_in[1];
    const float* emb = (const float*)d_in[2];
    const float* gW  = (const float*)d_in[3];
    const float* gb  = (const float*)d_in[4];
    const float* p1W = (const float*)d_in[5];
    const float* p1b = (const float*)d_in[6];
    const float* p2W = (const float*)d_in[7];
    const float* p2b = (const float*)d_in[8];
    const float* lng = (const float*)d_in[9];
    const float* lnb = (const float*)d_in[10];
    const float* Wih = (const float*)d_in[11];
    const float* Whh = (const float*)d_in[12];
    const float* bih = (const float*)d_in[13];
    const float* bhh = (const float*)d_in[14];
    float* out = (float*)d_out;

    static int attr_set = 0;
    if (!attr_set) {
        cudaFuncSetAttribute(k_gf, cudaFuncAttributeMaxDynamicSharedMemorySize, SMEM_GF);
        attr_set = 1;
    }

    k_wsum<<<512, 256>>>(Wih, Whh, bih, bhh);
    k_support<<<5, 256>>>(sp, emb, gW, gb, p1W, p1b, p2W, p2b, lng, lnb);
    k_s2mean<<<21, 128>>>(Whh);
    k_gather<<<NQ / 8, 256>>>(qp, emb);

    // step 0: gates = q@Wih.T + b (hl slot holds -q), c=0, no attn
    k_gf<<<NQ / 128, 256, SMEM_GF>>>(1, 0, 0);
    k_attn<<<NQ / 8, 256>>>();
    // steps 1,2
    k_gf<<<NQ / 128, 256, SMEM_GF>>>(0, 1, 0);
    k_attn<<<NQ / 8, 256>>>();
    k_gf<<<NQ / 128, 256, SMEM_GF>>>(0, 1, 0);
    k_attn<<<NQ / 8, 256>>>();
    // step 3 (last): no c store
    k_gf<<<NQ / 128, 256, SMEM_GF>>>(0, 1, 1);

    k_final<<<16384 / 8, 256>>>(out);
}

// round 13
// speedup vs baseline: 1.4196x; 1.4196x over previous
#include <cuda_runtime.h>
#include <cuda_fp16.h>
#include <math.h>

// ---------------- problem constants ----------------
#define NQ      32768      // BATCH*2 query rows
#define D       128
#define GW      512        // packed gate width: {i,f,g,o} x j<128 (j>=128 is dead)
#define FEW     5
#define SSTA    264        // A smem stride (halfs), K=256 + pad (conflict-free)
#define SSTB    136        // B smem stride (halfs), K=128 tile (conflict-free)

// k_gates smem layout (bytes)
#define OFF_BS    67584                 // As: 128*264*2
#define OFF_SS2H  102400                // Bs: 2 x 64*136*2 = 34816
#define OFF_SAT   107520                // sS2h: 5*512*2
#define OFF_BIAS  110080                // sAt: 128*5*4
#define SMEM_GATES 112128               // sBias: 512*4

// ---------------- scratch (static device arrays; no allocation) ----------------
__device__ float  d_SG[FEW * D];                 // support_g (5 x 128)
__device__ float  d_S2[FEW * GW];                // SG @ W2.T, packed 512 cols
__device__ float  d_MS[D];                       // mean_support
__device__ float  d_q   [(size_t)NQ * D];        // gathered query embeddings (fp32)
__device__ __half d_qhl [(size_t)NQ * 256];      // cols 0-127: q16 ; 128-255: hl16 (init -q)
__device__ float  d_hl  [(size_t)NQ * D];        // fp32 hl (last step only)
__device__ __half d_gates[(size_t)NQ * GW];      // packed per-step gates (fp16)
__device__ float  d_c   [(size_t)NQ * D];        // LSTM cell state, j<128 (fp32)
__device__ float  d_attn[(size_t)NQ * 8];        // attention weights (5, padded 8)
__device__ __half d_Wbig[GW * 256];              // [Wih+W1 | W1] packed 512x256 (fp16)
__device__ float  d_bsum[GW];                    // packed b_ih + b_hh

__device__ __forceinline__ float sigf(float x) {
    return __fdividef(1.0f, 1.0f + __expf(-x));
}
__device__ __forceinline__ float tanhfast(float x) {
    return __fdividef(2.0f, 1.0f + __expf(-2.0f * x)) - 1.0f;
}

__device__ __forceinline__ void mma_f16(float* c, const unsigned* a, unsigned b0, unsigned b1) {
    asm volatile(
        "mma.sync.aligned.m16n8k16.row.col.f32.f16.f16.f32 "
        "{%0,%1,%2,%3}, {%4,%5,%6,%7}, {%8,%9}, {%0,%1,%2,%3};"
        : "+f"(c[0]), "+f"(c[1]), "+f"(c[2]), "+f"(c[3])
        : "r"(a[0]), "r"(a[1]), "r"(a[2]), "r"(a[3]), "r"(b0), "r"(b1));
}

__device__ __forceinline__ void cpa16(void* smem, const void* gmem) {
    unsigned s = (unsigned)__cvta_generic_to_shared(smem);
    asm volatile("cp.async.cg.shared.global [%0], [%1], 16;" :: "r"(s), "l"(gmem));
}
#define CP_COMMIT() asm volatile("cp.async.commit_group;")
#define CP_WAIT(n)  asm volatile("cp.async.wait_group %0;" :: "n"(n))

// ---------------- prep: packed fp16 Wbig = [Wih + W1 | W1] / bsum ----------------
// packed row pr in [0,512): gate = pr>>7, j = pr&127 ; original row = gate*256 + j
__global__ void k_wsum(const float* __restrict__ Wih, const float* __restrict__ Whh,
                       const float* __restrict__ bih, const float* __restrict__ bhh) {
    int idx = blockIdx.x * 256 + threadIdx.x;           // 512*256 = 131072
    int pr = idx >> 8, k = idx & 255;
    int orig = ((pr >> 7) << 8) + (pr & 127);           // gate*256 + j
    float val;
    if (k < 128) val = Wih[(size_t)orig * 128 + k] + Whh[(size_t)orig * 256 + k];
    else         val = Whh[(size_t)orig * 256 + (k - 128)];
    d_Wbig[idx] = __float2half_rn(val);
    if (idx < GW) {
        int o2 = ((idx >> 7) << 8) + (idx & 127);
        d_bsum[idx] = bih[o2] + bhh[o2];
    }
}

// ---------------- support path: GCN (linear!) + MLP + LayerNorm ----------------
__global__ void k_support(const int* __restrict__ sp, const float* __restrict__ emb,
                          const float* __restrict__ gW, const float* __restrict__ gb,
                          const float* __restrict__ p1W, const float* __restrict__ p1b,
                          const float* __restrict__ p2W, const float* __restrict__ p2b,
                          const float* __restrict__ lng, const float* __restrict__ lnb) {
    __shared__ float cs[256], s[128], h1[256], x[128], stat[2];
    int f = blockIdx.x, t = threadIdx.x;
    int side = t >> 7, col = t & 127;
    const int* pf = sp + f * 400;
    float acc = 0.f;
    #pragma unroll 4
    for (int n = 0; n < 200; n++) {
        int idx = pf[n * 2 + side];
        acc += emb[(size_t)idx * 128 + col];
    }
    cs[t] = acc;
    __syncthreads();
    if (t < 128) {
        float a = 200.f * gb[t];
        #pragma unroll 4
        for (int k = 0; k < 256; k++) a = fmaf(cs[k], gW[t * 256 + k], a);
        s[t] = tanhf(a * 0.2f);
    }
    __syncthreads();
    {
        float a = p1b[t];
        #pragma unroll 4
        for (int j = 0; j < 128; j++) a = fmaf(s[j], p1W[t * 128 + j], a);
        h1[t] = fmaxf(a, 0.f);
    }
    __syncthreads();
    if (t < 128) {
        float a = p2b[t];
        #pragma unroll 4
        for (int k = 0; k < 256; k++) a = fmaf(h1[k], p2W[t * 256 + k], a);
        x[t] = a + s[t];
    }
    __syncthreads();
    if (t == 0) {
        float mu = 0.f;
        for (int j = 0; j < 128; j++) mu += x[j];
        mu *= (1.f / 128.f);
        float v = 0.f;
        for (int j = 0; j < 128; j++) { float dd = x[j] - mu; v += dd * dd; }
        v *= (1.f / 128.f);
        stat[0] = mu; stat[1] = rsqrtf(v + 1e-5f);
    }
    __syncthreads();
    if (t < 128) d_SG[f * 128 + t] = lng[t] * (x[t] - stat[0]) * stat[1] + lnb[t];
}

// ---------------- S2 (packed 512 cols) + mean_support ----------------
__global__ void k_s2mean(const float* __restrict__ Whh) {
    __shared__ float sg[128];
    int b = blockIdx.x, t = threadIdx.x;
    if (b < 20) {
        int f = b >> 2, gbk = b & 3;
        sg[t] = d_SG[f * 128 + t];
        __syncthreads();
        int pc = gbk * 128 + t;
        int orig = ((pc >> 7) << 8) + (pc & 127);
        float a = 0.f;
        #pragma unroll 4
        for (int j = 0; j < 128; j++) a = fmaf(sg[j], Whh[(size_t)orig * 256 + 128 + j], a);
        d_S2[f * GW + pc] = a;
    } else {
        float a = 0.f;
        #pragma unroll
        for (int f = 0; f < FEW; f++) a += d_SG[f * 128 + t];
        d_MS[t] = a * 0.2f;
    }
}

// ---------------- gather: q fp32, qhl = [q16 | -q16] (step-0 trick) ----------------
__global__ void k_gather(const int* __restrict__ qp, const float* __restrict__ emb) {
    int row = blockIdx.x * 8 + (threadIdx.x >> 5);
    int lane = threadIdx.x & 31;
    int idx = qp[row];
    float4 v = *(const float4*)(emb + (size_t)idx * 128 + lane * 4);
    *(float4*)(d_q + (size_t)row * 128 + lane * 4) = v;
    __half* qr = d_qhl + (size_t)row * 256;
    *(__half2*)(qr + lane * 4)           = __floats2half2_rn(v.x, v.y);
    *(__half2*)(qr + lane * 4 + 2)       = __floats2half2_rn(v.z, v.w);
    *(__half2*)(qr + 128 + lane * 4)     = __floats2half2_rn(-v.x, -v.y);
    *(__half2*)(qr + 128 + lane * 4 + 2) = __floats2half2_rn(-v.z, -v.w);
}

// ---------------- step GEMM: cp.async double-buffered B, 8 N-tiles of 64 x 2 K-halves ----
// gates = [q|hl] @ [Wc|W1].T + b (+ attn@S2). Block = 128 rows; warp tile 32x32.
__global__ void __launch_bounds__(256, 2) k_gates(int hasattn) {
    extern __shared__ char smraw[];
    __half* As   = (__half*)smraw;                       // 128 x 264
    __half* Bsb  = (__half*)(smraw + OFF_BS);            // 2 x (64 x 136)
    __half* sS2h = (__half*)(smraw + OFF_SS2H);          // 5 x 512
    float*  sAt  = (float*)(smraw + OFF_SAT);            // 128 x 5
    float*  sBias= (float*)(smraw + OFF_BIAS);           // 512

    int by = blockIdx.x;
    int tid = threadIdx.x, lane = tid & 31, warp = tid >> 5;
    int g = lane >> 2, tg = lane & 3;
    int wm = warp >> 1, wn = warp & 1;                   // 4(M) x 2(N); warp tile 32 x 32

    // A tile via cp.async (group 0, together with B tile 0)
    const __half* Ag = d_qhl + (size_t)by * 128 * 256;
    #pragma unroll
    for (int it = 0; it < 16; it++) {
        int i = tid + it * 256; int r = i >> 5, c8 = (i & 31) << 3;
        cpa16(As + r * SSTA + c8, Ag + r * 256 + c8);
    }
    // B tile 0 (nn=0, kh=0) into buffer 0
    {
        const __half* Bg = d_Wbig;
        #pragma unroll
        for (int it = 0; it < 4; it++) {
            int i = tid + it * 256; int r = i >> 4, c8 = (i & 15) << 3;
            cpa16(Bsb + r * SSTB + c8, Bg + (size_t)r * 256 + c8);
        }
    }
    CP_COMMIT();

    // regular smem fills (visible after first __syncthreads)
    if (hasattn) {
        for (int i = tid; i < FEW * GW; i += 256) sS2h[i] = __float2half_rn(d_S2[i]);
        for (int i = tid; i < 128 * FEW; i += 256) {
            int r = i / FEW, f = i - r * FEW;
            sAt[i] = d_attn[(size_t)(by * 128 + r) * 8 + f];
        }
    }
    for (int i = tid; i < GW; i += 256) sBias[i] = d_bsum[i];

    float acc[2][4][4];
    #pragma unroll 1
    for (int ph = 0; ph < 16; ph++) {
        int nn = ph >> 1, kh = ph & 1;
        if (ph < 15) {                                   // prefetch next tile
            int nn2 = (ph + 1) >> 1, kh2 = (ph + 1) & 1;
            const __half* Bg = d_Wbig + (size_t)(nn2 * 64) * 256 + kh2 * 128;
            __half* dst = Bsb + ((ph + 1) & 1) * (64 * SSTB);
            #pragma unroll
            for (int it = 0; it < 4; it++) {
                int i = tid + it * 256; int r = i >> 4, c8 = (i & 15) << 3;
                cpa16(dst + r * SSTB + c8, Bg + (size_t)r * 256 + c8);
            }
            CP_COMMIT();
            CP_WAIT(1);
        } else {
            CP_WAIT(0);
        }
        __syncthreads();                                 // current buffer ready

        if (kh == 0) {
            #pragma unroll
            for (int mi = 0; mi < 2; mi++)
                #pragma unroll
                for (int ni = 0; ni < 4; ni++)
                    #pragma unroll
                    for (int r = 0; r < 4; r++) acc[mi][ni][r] = 0.f;
        }

        const __half* Bs = Bsb + (ph & 1) * (64 * SSTB);
        #pragma unroll
        for (int kk = 0; kk < 8; kk++) {
            int ca = kh * 128 + kk * 16 + 2 * tg;
            int cb = kk * 16 + 2 * tg;
            unsigned a[2][4];
            #pragma unroll
            for (int mi = 0; mi < 2; mi++) {
                const __half* p = As + (wm * 32 + mi * 16 + g) * SSTA + ca;
                a[mi][0] = *(const unsigned*)(p);
                a[mi][1] = *(const unsigned*)(p + 8 * SSTA);
                a[mi][2] = *(const unsigned*)(p + 8);
                a[mi][3] = *(const unsigned*)(p + 8 * SSTA + 8);
            }
            #pragma unroll
            for (int ni = 0; ni < 4; ni++) {
                const __half* p = Bs + (wn * 32 + ni * 8 + g) * SSTB + cb;
                unsigned b0 = *(const unsigned*)(p);
                unsigned b1 = *(const unsigned*)(p + 8);
                #pragma unroll
                for (int mi = 0; mi < 2; mi++)
                    mma_f16(acc[mi][ni], a[mi], b0, b1);
            }
        }
        __syncthreads();                                 // done reading this buffer

        if (kh == 1) {                                   // epilogue for N-tile nn
            #pragma unroll
            for (int mi = 0; mi < 2; mi++) {
                #pragma unroll
                for (int ni = 0; ni < 4; ni++) {
                    int rl0 = wm * 32 + mi * 16 + g;
                    int cit = wn * 32 + ni * 8 + 2 * tg;
                    int gcol = nn * 64 + cit;
                    #pragma unroll
                    for (int rr = 0; rr < 2; rr++) {
                        int rl = rl0 + rr * 8;
                        size_t row = (size_t)(by * 128 + rl);
                        float x0 = acc[mi][ni][rr * 2 + 0] + sBias[gcol];
                        float x1 = acc[mi][ni][rr * 2 + 1] + sBias[gcol + 1];
                        if (hasattn) {
                            #pragma unroll
                            for (int f = 0; f < FEW; f++) {
                                float av = sAt[rl * FEW + f];
                                x0 = fmaf(av, __half2float(sS2h[f * GW + gcol]), x0);
                                x1 = fmaf(av, __half2float(sS2h[f * GW + gcol + 1]), x1);
                            }
                        }
                        *(__half2*)(d_gates + row * GW + gcol) = __floats2half2_rn(x0, x1);
                    }
                }
            }
        }
    }
}

// ---------------- vectorized LSTM update (j<128) + attention softmax ----------------
__global__ void __launch_bounds__(256) k_lstm(int first) {
    __shared__ float sSg[FEW * 128];
    for (int i = threadIdx.x; i < FEW * 128; i += 256) sSg[i] = d_SG[i];
    __syncthreads();
    int row = blockIdx.x * 8 + (threadIdx.x >> 5);
    int lane = threadIdx.x & 31;
    int j0 = lane * 4;
    const __half* gr = d_gates + (size_t)row * GW;
    uint2 ri = *(const uint2*)(gr + j0);
    uint2 rf = *(const uint2*)(gr + 128 + j0);
    uint2 rg = *(const uint2*)(gr + 256 + j0);
    uint2 ro = *(const uint2*)(gr + 384 + j0);
    float2 i01 = __half22float2(*(__half2*)&ri.x), i23 = __half22float2(*(__half2*)&ri.y);
    float2 f01 = __half22float2(*(__half2*)&rf.x), f23 = __half22float2(*(__half2*)&rf.y);
    float2 g01 = __half22float2(*(__half2*)&rg.x), g23 = __half22float2(*(__half2*)&rg.y);
    float2 o01 = __half22float2(*(__half2*)&ro.x), o23 = __half22float2(*(__half2*)&ro.y);
    float gi[4] = {i01.x, i01.y, i23.x, i23.y};
    float gf[4] = {f01.x, f01.y, f23.x, f23.y};
    float gg[4] = {g01.x, g01.y, g23.x, g23.y};
    float go[4] = {o01.x, o01.y, o23.x, o23.y};
    float4 co4 = make_float4(0.f, 0.f, 0.f, 0.f);
    if (!first) co4 = *(const float4*)(d_c + (size_t)row * 128 + j0);
    float co[4] = {co4.x, co4.y, co4.z, co4.w};
    float cn[4], hl[4];
    #pragma unroll
    for (int k = 0; k < 4; k++) {
        cn[k] = fmaf(sigf(gf[k]), co[k], sigf(gi[k]) * tanhfast(gg[k]));
        hl[k] = sigf(go[k]) * tanhfast(cn[k]);
    }
    *(float4*)(d_c + (size_t)row * 128 + j0) = make_float4(cn[0], cn[1], cn[2], cn[3]);
    __half* qr = d_qhl + (size_t)row * 256;
    uint2 q2 = *(const uint2*)(qr + j0);
    float2 q01 = __half22float2(*(__half2*)&q2.x), q23 = __half22float2(*(__half2*)&q2.y);
    float hq[4] = {q01.x + hl[0], q01.y + hl[1], q23.x + hl[2], q23.y + hl[3]};
    __half2 h01 = __floats2half2_rn(hl[0], hl[1]);
    __half2 h23 = __floats2half2_rn(hl[2], hl[3]);
    uint2 ho; ho.x = *(unsigned*)&h01; ho.y = *(unsigned*)&h23;
    *(uint2*)(qr + 128 + j0) = ho;
    float part[FEW];
    #pragma unroll
    for (int f = 0; f < FEW; f++) {
        float a = 0.f;
        #pragma unroll
        for (int k = 0; k < 4; k++) a = fmaf(hq[k], sSg[f * 128 + j0 + k], a);
        part[f] = a;
    }
    #pragma unroll
    for (int o = 16; o; o >>= 1)
        #pragma unroll
        for (int f = 0; f < FEW; f++) part[f] += __shfl_xor_sync(0xffffffffu, part[f], o);
    if (lane == 0) {
        float m = part[0];
        #pragma unroll
        for (int f = 1; f < FEW; f++) m = fmaxf(m, part[f]);
        float e[FEW], ss = 0.f;
        #pragma unroll
        for (int f = 0; f < FEW; f++) { e[f] = __expf(part[f] - m); ss += e[f]; }
        float inv = __fdividef(1.f, ss);
        #pragma unroll
        for (int f = 0; f < FEW; f++) d_attn[(size_t)row * 8 + f] = e[f] * inv;
    }
}

// last step: no attention, no c store; hl written fp32 for k_final
__global__ void __launch_bounds__(256) k_lstm_last() {
    int row = blockIdx.x * 8 + (threadIdx.x >> 5);
    int lane = threadIdx.x & 31;
    int j0 = lane * 4;
    const __half* gr = d_gates + (size_t)row * GW;
    uint2 ri = *(const uint2*)(gr + j0);
    uint2 rf = *(const uint2*)(gr + 128 + j0);
    uint2 rg = *(const uint2*)(gr + 256 + j0);
    uint2 ro = *(const uint2*)(gr + 384 + j0);
    float2 i01 = __half22float2(*(__half2*)&ri.x), i23 = __half22float2(*(__half2*)&ri.y);
    float2 f01 = __half22float2(*(__half2*)&rf.x), f23 = __half22float2(*(__half2*)&rf.y);
    float2 g01 = __half22float2(*(__half2*)&rg.x), g23 = __half22float2(*(__half2*)&rg.y);
    float2 o01 = __half22float2(*(__half2*)&ro.x), o23 = __half22float2(*(__half2*)&ro.y);
    float gi[4] = {i01.x, i01.y, i23.x, i23.y};
    float gf[4] = {f01.x, f01.y, f23.x, f23.y};
    float gg[4] = {g01.x, g01.y, g23.x, g23.y};
    float go[4] = {o01.x, o01.y, o23.x, o23.y};
    float4 co4 = *(const float4*)(d_c + (size_t)row * 128 + j0);
    float co[4] = {co4.x, co4.y, co4.z, co4.w};
    float hl[4];
    #pragma unroll
    for (int k = 0; k < 4; k++) {
        float cn = fmaf(sigf(gf[k]), co[k], sigf(gi[k]) * tanhfast(gg[k]));
        hl[k] = sigf(go[k]) * tanhfast(cn);
    }
    *(float4*)(d_hl + (size_t)row * 128 + j0) = make_float4(hl[0], hl[1], hl[2], hl[3]);
}

// ---------------- final: out[b] = mean(hq[2b], hq[2b+1]) . mean_support ----------------
__global__ void k_final(float* __restrict__ out) {
    __shared__ float ms[128];
    int t = threadIdx.x;
    if (t < 128) ms[t] = d_MS[t];
    __syncthreads();
    int b = blockIdx.x * 8 + (t >> 5);
    int lane = t & 31;
    const float* q0 = d_q  + (size_t)b * 256;
    const float* h0 = d_hl + (size_t)b * 256;
    int j = lane * 4;
    float4 qa = *(const float4*)(q0 + j);
    float4 qb = *(const float4*)(q0 + 128 + j);
    float4 ha = *(const float4*)(h0 + j);
    float4 hb = *(const float4*)(h0 + 128 + j);
    float4 m4 = *(const float4*)(ms + j);
    float p = 0.5f * ((qa.x + ha.x + qb.x + hb.x) * m4.x +
                      (qa.y + ha.y + qb.y + hb.y) * m4.y +
                      (qa.z + ha.z + qb.z + hb.z) * m4.z +
                      (qa.w + ha.w + qb.w + hb.w) * m4.w);
    #pragma unroll
    for (int o = 16; o; o >>= 1) p += __shfl_xor_sync(0xffffffffu, p, o);
    if (lane == 0) out[b] = p;
}

// ---------------- launcher ----------------
extern "C" void kernel_launch(void* const* d_in, const int* in_sizes, int n_in,
                              void* d_out, int out_size) {
    const int*   qp  = (const int*)d_in[0];
    const int*   sp  = (const int*)d_in[1];
    const float* emb = (const float*)d_in[2];
    const float* gW  = (const float*)d_in[3];
    const float* gb  = (const float*)d_in[4];
    const float* p1W = (const float*)d_in[5];
    const float* p1b = (const float*)d_in[6];
    const float* p2W = (const float*)d_in[7];
    const float* p2b = (const float*)d_in[8];
    const float* lng = (const float*)d_in[9];
    const float* lnb = (const float*)d_in[10];
    const float* Wih = (const float*)d_in[11];
    const float* Whh = (const float*)d_in[12];
    const float* bih = (const float*)d_in[13];
    const float* bhh = (const float*)d_in[14];
    float* out = (float*)d_out;

    static int attr_set = 0;
    if (!attr_set) {
        cudaFuncSetAttribute(k_gates, cudaFuncAttributeMaxDynamicSharedMemorySize, SMEM_GATES);
        attr_set = 1;
    }

    k_wsum<<<512, 256>>>(Wih, Whh, bih, bhh);
    k_support<<<5, 256>>>(sp, emb, gW, gb, p1W, p1b, p2W, p2b, lng, lnb);
    k_s2mean<<<21, 128>>>(Whh);
    k_gather<<<NQ / 8, 256>>>(qp, emb);

    // step 0: gates = q@Wih.T + b  (hl slot holds -q), no attn
    k_gates<<<NQ / 128, 256, SMEM_GATES>>>(0);
    k_lstm<<<NQ / 8, 256>>>(1);

    // steps 1,2: gates = q@Wc.T + hl@W1.T + b + attn@S2
    k_gates<<<NQ / 128, 256, SMEM_GATES>>>(1);
    k_lstm<<<NQ / 8, 256>>>(0);
    k_gates<<<NQ / 128, 256, SMEM_GATES>>>(1);
    k_lstm<<<NQ / 8, 256>>>(0);

    // step 3 (last)
    k_gates<<<NQ / 128, 256, SMEM_GATES>>>(1);
    k_lstm_last<<<NQ / 8, 256>>>();

    k_final<<<16384 / 8, 256>>>(out);
}

// round 15
// speedup vs baseline: 1.5064x; 1.0612x over previous
#include <cuda_runtime.h>
#include <cuda_fp16.h>
#include <math.h>

// ---------------- problem constants ----------------
#define NQ      32768      // BATCH*2 query rows
#define D       128
#define GW      512        // packed gate width: {i,f,g,o} x j<128 (j>=128 is dead)
#define FEW     5
#define SSTA    264        // A smem stride (halfs): 528B/row = 4 banks/row -> CF
#define SSTB    136        // B smem stride (halfs): 272B/row = 4 banks/row -> CF

// k_gates smem layout (bytes)
#define OFF_BS    67584                 // As: 128*264*2
#define OFF_SS2H  102400                // Bs: 128*136*2 = 34816
#define OFF_SAT   107520                // sS2h: 5*512*2
#define OFF_BIAS  110080                // sAt: 128*5*4
#define SMEM_GATES 112128               // sBias: 512*4

// ---------------- scratch (static device arrays; no allocation) ----------------
__device__ float  d_SG[FEW * D];                 // support_g (5 x 128)
__device__ float  d_S2[FEW * GW];                // SG @ W2.T, packed 512 cols
__device__ float  d_MS[D];                       // mean_support
__device__ float  d_q   [(size_t)NQ * D];        // gathered query embeddings (fp32)
__device__ __half d_qhl [(size_t)NQ * 256];      // cols 0-127: q16 ; 128-255: hl16 (init -q)
__device__ float  d_hl  [(size_t)NQ * D];        // fp32 hl (last step only)
__device__ __half d_gates[(size_t)NQ * GW];      // packed per-step gates (fp16)
__device__ float  d_c   [(size_t)NQ * D];        // LSTM cell state, j<128 (fp32)
__device__ float  d_attn[(size_t)NQ * 8];        // attention weights (5, padded 8)
__device__ __half d_Wbig[GW * 256];              // [Wih+W1 | W1] packed 512x256 (fp16)
__device__ float  d_bsum[GW];                    // packed b_ih + b_hh

__device__ __forceinline__ float sigf(float x) {
    return __fdividef(1.0f, 1.0f + __expf(-x));
}
__device__ __forceinline__ float tanhfast(float x) {
    return __fdividef(2.0f, 1.0f + __expf(-2.0f * x)) - 1.0f;
}

__device__ __forceinline__ void mma_f16(float* c, const unsigned* a, unsigned b0, unsigned b1) {
    asm volatile(
        "mma.sync.aligned.m16n8k16.row.col.f32.f16.f16.f32 "
        "{%0,%1,%2,%3}, {%4,%5,%6,%7}, {%8,%9}, {%0,%1,%2,%3};"
        : "+f"(c[0]), "+f"(c[1]), "+f"(c[2]), "+f"(c[3])
        : "r"(a[0]), "r"(a[1]), "r"(a[2]), "r"(a[3]), "r"(b0), "r"(b1));
}

__device__ __forceinline__ void ldsm_x4(unsigned& r0, unsigned& r1, unsigned& r2, unsigned& r3,
                                        unsigned addr) {
    asm volatile("ldmatrix.sync.aligned.m8n8.x4.shared.b16 {%0,%1,%2,%3}, [%4];"
                 : "=r"(r0), "=r"(r1), "=r"(r2), "=r"(r3) : "r"(addr));
}
__device__ __forceinline__ unsigned smem_u32(const void* p) {
    return (unsigned)__cvta_generic_to_shared(p);
}

// ---------------- prep: packed fp16 Wbig / bsum  +  gather (merged) ----------------
// packed row pr in [0,512): gate = pr>>7, j = pr&127 ; original row = gate*256 + j
__global__ void k_prep(const float* __restrict__ Wih, const float* __restrict__ Whh,
                       const float* __restrict__ bih, const float* __restrict__ bhh,
                       const int* __restrict__ qp, const float* __restrict__ emb) {
    if (blockIdx.x < 512) {                              // weight pack part
        int idx = blockIdx.x * 256 + threadIdx.x;        // 512*256 = 131072
        int pr = idx >> 8, k = idx & 255;
        int orig = ((pr >> 7) << 8) + (pr & 127);        // gate*256 + j
        float val;
        if (k < 128) val = Wih[(size_t)orig * 128 + k] + Whh[(size_t)orig * 256 + k];
        else         val = Whh[(size_t)orig * 256 + (k - 128)];
        d_Wbig[idx] = __float2half_rn(val);
        if (idx < GW) {
            int o2 = ((idx >> 7) << 8) + (idx & 127);
            d_bsum[idx] = bih[o2] + bhh[o2];
        }
    } else {                                             // gather part
        int row = (blockIdx.x - 512) * 8 + (threadIdx.x >> 5);
        int lane = threadIdx.x & 31;
        int idx = qp[row];
        float4 v = *(const float4*)(emb + (size_t)idx * 128 + lane * 4);
        *(float4*)(d_q + (size_t)row * 128 + lane * 4) = v;
        __half* qr = d_qhl + (size_t)row * 256;
        *(__half2*)(qr + lane * 4)           = __floats2half2_rn(v.x, v.y);
        *(__half2*)(qr + lane * 4 + 2)       = __floats2half2_rn(v.z, v.w);
        *(__half2*)(qr + 128 + lane * 4)     = __floats2half2_rn(-v.x, -v.y);
        *(__half2*)(qr + 128 + lane * 4 + 2) = __floats2half2_rn(-v.z, -v.w);
    }
}

// ---------------- support path: GCN (linear!) + MLP + LayerNorm ----------------
__global__ void k_support(const int* __restrict__ sp, const float* __restrict__ emb,
                          const float* __restrict__ gW, const float* __restrict__ gb,
                          const float* __restrict__ p1W, const float* __restrict__ p1b,
                          const float* __restrict__ p2W, const float* __restrict__ p2b,
                          const float* __restrict__ lng, const float* __restrict__ lnb) {
    __shared__ float cs[256], s[128], h1[256], x[128], stat[2];
    int f = blockIdx.x, t = threadIdx.x;
    int side = t >> 7, col = t & 127;
    const int* pf = sp + f * 400;
    float acc = 0.f;
    #pragma unroll 4
    for (int n = 0; n < 200; n++) {
        int idx = pf[n * 2 + side];
        acc += emb[(size_t)idx * 128 + col];
    }
    cs[t] = acc;
    __syncthreads();
    if (t < 128) {
        float a = 200.f * gb[t];
        #pragma unroll 4
        for (int k = 0; k < 256; k++) a = fmaf(cs[k], gW[t * 256 + k], a);
        s[t] = tanhf(a * 0.2f);
    }
    __syncthreads();
    {
        float a = p1b[t];
        #pragma unroll 4
        for (int j = 0; j < 128; j++) a = fmaf(s[j], p1W[t * 128 + j], a);
        h1[t] = fmaxf(a, 0.f);
    }
    __syncthreads();
    if (t < 128) {
        float a = p2b[t];
        #pragma unroll 4
        for (int k = 0; k < 256; k++) a = fmaf(h1[k], p2W[t * 256 + k], a);
        x[t] = a + s[t];
    }
    __syncthreads();
    if (t == 0) {
        float mu = 0.f;
        for (int j = 0; j < 128; j++) mu += x[j];
        mu *= (1.f / 128.f);
        float v = 0.f;
        for (int j = 0; j < 128; j++) { float dd = x[j] - mu; v += dd * dd; }
        v *= (1.f / 128.f);
        stat[0] = mu; stat[1] = rsqrtf(v + 1e-5f);
    }
    __syncthreads();
    if (t < 128) d_SG[f * 128 + t] = lng[t] * (x[t] - stat[0]) * stat[1] + lnb[t];
}

// ---------------- S2 (packed 512 cols) + mean_support ----------------
__global__ void k_s2mean(const float* __restrict__ Whh) {
    __shared__ float sg[128];
    int b = blockIdx.x, t = threadIdx.x;
    if (b < 20) {
        int f = b >> 2, gbk = b & 3;
        sg[t] = d_SG[f * 128 + t];
        __syncthreads();
        int pc = gbk * 128 + t;
        int orig = ((pc >> 7) << 8) + (pc & 127);
        float a = 0.f;
        #pragma unroll 4
        for (int j = 0; j < 128; j++) a = fmaf(sg[j], Whh[(size_t)orig * 256 + 128 + j], a);
        d_S2[f * GW + pc] = a;
    } else {
        float a = 0.f;
        #pragma unroll
        for (int f = 0; f < FEW; f++) a += d_SG[f * 128 + t];
        d_MS[t] = a * 0.2f;
    }
}

// ---------------- step GEMM: ldmatrix + m16n8k16, 128 rows/block, 4 N tiles ----------
// gates = [q|hl] @ [Wc|W1].T + b (+ attn@S2). Warps 2(M) x 4(N); warp tile 64 x 32.
__global__ void __launch_bounds__(256, 2) k_gates(int hasattn) {
    extern __shared__ char smraw[];
    __half* As   = (__half*)smraw;                       // 128 x 264
    __half* Bs   = (__half*)(smraw + OFF_BS);            // 128 x 136
    __half* sS2h = (__half*)(smraw + OFF_SS2H);          // 5 x 512
    float*  sAt  = (float*)(smraw + OFF_SAT);            // 128 x 5
    float*  sBias= (float*)(smraw + OFF_BIAS);           // 512

    int by = blockIdx.x;
    int tid = threadIdx.x, lane = tid & 31, warp = tid >> 5;
    int g = lane >> 2, tg = lane & 3;
    int wm = warp >> 2, wn = warp & 3;                   // 2(M) x 4(N)

    // A tile: 128 rows x 256 halfs (q | hl)
    const __half* Ag = d_qhl + (size_t)by * 128 * 256;
    #pragma unroll
    for (int it = 0; it < 16; it++) {
        int i = tid + it * 256; int r = i >> 5, c8 = (i & 31) << 3;
        *(uint4*)(As + r * SSTA + c8) = *(const uint4*)(Ag + r * 256 + c8);
    }
    if (hasattn) {
        for (int i = tid; i < FEW * GW; i += 256) sS2h[i] = __float2half_rn(d_S2[i]);
        for (int i = tid; i < 128 * FEW; i += 256) {
            int r = i / FEW, f = i - r * FEW;
            sAt[i] = d_attn[(size_t)(by * 128 + r) * 8 + f];
        }
    }
    for (int i = tid; i < GW; i += 256) sBias[i] = d_bsum[i];

    // ldmatrix per-lane base addresses
    int arow = lane & 15;                                // rows 0-15 within fragment
    int ach  = (lane >> 4) << 3;                         // col-half 0/8 (halfs)
    unsigned abase[4];
    #pragma unroll
    for (int mi = 0; mi < 4; mi++)
        abase[mi] = smem_u32(As + (wm * 64 + mi * 16 + arow) * SSTA + ach);
    int bn  = (lane & 7) + ((lane & 16) ? 8 : 0);        // n within 16
    int bkh = ((lane >> 3) & 1) << 3;                    // k-half 0/8
    unsigned bbase[2];
    #pragma unroll
    for (int p = 0; p < 2; p++)
        bbase[p] = smem_u32(Bs + (wn * 32 + p * 16 + bn) * SSTB + bkh);

    for (int nn = 0; nn < 4; nn++) {
        float acc[4][4][4];
        #pragma unroll
        for (int mi = 0; mi < 4; mi++)
            #pragma unroll
            for (int ni = 0; ni < 4; ni++)
                #pragma unroll
                for (int r = 0; r < 4; r++) acc[mi][ni][r] = 0.f;

        #pragma unroll
        for (int kh = 0; kh < 2; kh++) {
            __syncthreads();                             // prev MMA done with Bs
            const __half* Bg = d_Wbig + (size_t)(nn * 128) * 256 + kh * 128;
            #pragma unroll
            for (int it = 0; it < 8; it++) {
                int i = tid + it * 256; int r = i >> 4, c8 = (i & 15) << 3;
                *(uint4*)(Bs + r * SSTB + c8) = *(const uint4*)(Bg + (size_t)r * 256 + c8);
            }
            __syncthreads();

            #pragma unroll
            for (int kk = 0; kk < 8; kk++) {
                unsigned aoff = (unsigned)((kh * 128 + kk * 16) * 2);  // bytes
                unsigned boff = (unsigned)(kk * 16 * 2);
                unsigned a[4][4];
                #pragma unroll
                for (int mi = 0; mi < 4; mi++)
                    ldsm_x4(a[mi][0], a[mi][1], a[mi][2], a[mi][3], abase[mi] + aoff);
                unsigned b[4][2];
                #pragma unroll
                for (int p = 0; p < 2; p++)
                    ldsm_x4(b[2 * p][0], b[2 * p][1], b[2 * p + 1][0], b[2 * p + 1][1],
                            bbase[p] + boff);
                #pragma unroll
                for (int ni = 0; ni < 4; ni++)
                    #pragma unroll
                    for (int mi = 0; mi < 4; mi++)
                        mma_f16(acc[mi][ni], a[mi], b[ni][0], b[ni][1]);
            }
        }

        // epilogue for this N tile
        #pragma unroll
        for (int mi = 0; mi < 4; mi++) {
            #pragma unroll
            for (int ni = 0; ni < 4; ni++) {
                int rl0 = wm * 64 + mi * 16 + g;
                int cit = wn * 32 + ni * 8 + 2 * tg;
                int gcol = nn * 128 + cit;
                #pragma unroll
                for (int rr = 0; rr < 2; rr++) {
                    int rl = rl0 + rr * 8;
                    size_t row = (size_t)(by * 128 + rl);
                    float x0 = acc[mi][ni][rr * 2 + 0] + sBias[gcol];
                    float x1 = acc[mi][ni][rr * 2 + 1] + sBias[gcol + 1];
                    if (hasattn) {
                        #pragma unroll
                        for (int f = 0; f < FEW; f++) {
                            float av = sAt[rl * FEW + f];
                            float2 s2 = __half22float2(*(const __half2*)(sS2h + f * GW + gcol));
                            x0 = fmaf(av, s2.x, x0);
                            x1 = fmaf(av, s2.y, x1);
                        }
                    }
                    *(__half2*)(d_gates + row * GW + gcol) = __floats2half2_rn(x0, x1);
                }
            }
        }
    }
}

// ---------------- vectorized LSTM update (j<128) + attention softmax ----------------
__global__ void __launch_bounds__(256) k_lstm(int first) {
    __shared__ float sSg[FEW * 128];
    for (int i = threadIdx.x; i < FEW * 128; i += 256) sSg[i] = d_SG[i];
    __syncthreads();
    int row = blockIdx.x * 8 + (threadIdx.x >> 5);
    int lane = threadIdx.x & 31;
    int j0 = lane * 4;
    const __half* gr = d_gates + (size_t)row * GW;
    uint2 ri = *(const uint2*)(gr + j0);
    uint2 rf = *(const uint2*)(gr + 128 + j0);
    uint2 rg = *(const uint2*)(gr + 256 + j0);
    uint2 ro = *(const uint2*)(gr + 384 + j0);
    float2 i01 = __half22float2(*(__half2*)&ri.x), i23 = __half22float2(*(__half2*)&ri.y);
    float2 f01 = __half22float2(*(__half2*)&rf.x), f23 = __half22float2(*(__half2*)&rf.y);
    float2 g01 = __half22float2(*(__half2*)&rg.x), g23 = __half22float2(*(__half2*)&rg.y);
    float2 o01 = __half22float2(*(__half2*)&ro.x), o23 = __half22float2(*(__half2*)&ro.y);
    float gi[4] = {i01.x, i01.y, i23.x, i23.y};
    float gf[4] = {f01.x, f01.y, f23.x, f23.y};
    float gg[4] = {g01.x, g01.y, g23.x, g23.y};
    float go[4] = {o01.x, o01.y, o23.x, o23.y};
    float4 co4 = make_float4(0.f, 0.f, 0.f, 0.f);
    if (!first) co4 = *(const float4*)(d_c + (size_t)row * 128 + j0);
    float co[4] = {co4.x, co4.y, co4.z, co4.w};
    float cn[4], hl[4];
    #pragma unroll
    for (int k = 0; k < 4; k++) {
        cn[k] = fmaf(sigf(gf[k]), co[k], sigf(gi[k]) * tanhfast(gg[k]));
        hl[k] = sigf(go[k]) * tanhfast(cn[k]);
    }
    *(float4*)(d_c + (size_t)row * 128 + j0) = make_float4(cn[0], cn[1], cn[2], cn[3]);
    __half* qr = d_qhl + (size_t)row * 256;
    uint2 q2 = *(const uint2*)(qr + j0);
    float2 q01 = __half22float2(*(__half2*)&q2.x), q23 = __half22float2(*(__half2*)&q2.y);
    float hq[4] = {q01.x + hl[0], q01.y + hl[1], q23.x + hl[2], q23.y + hl[3]};
    __half2 h01 = __floats2half2_rn(hl[0], hl[1]);
    __half2 h23 = __floats2half2_rn(hl[2], hl[3]);
    uint2 ho; ho.x = *(unsigned*)&h01; ho.y = *(unsigned*)&h23;
    *(uint2*)(qr + 128 + j0) = ho;
    float part[FEW];
    #pragma unroll
    for (int f = 0; f < FEW; f++) {
        float a = 0.f;
        #pragma unroll
        for (int k = 0; k < 4; k++) a = fmaf(hq[k], sSg[f * 128 + j0 + k], a);
        part[f] = a;
    }
    #pragma unroll
    for (int o = 16; o; o >>= 1)
        #pragma unroll
        for (int f = 0; f < FEW; f++) part[f] += __shfl_xor_sync(0xffffffffu, part[f], o);
    if (lane == 0) {
        float m = part[0];
        #pragma unroll
        for (int f = 1; f < FEW; f++) m = fmaxf(m, part[f]);
        float e[FEW], ss = 0.f;
        #pragma unroll
        for (int f = 0; f < FEW; f++) { e[f] = __expf(part[f] - m); ss += e[f]; }
        float inv = __fdividef(1.f, ss);
        #pragma unroll
        for (int f = 0; f < FEW; f++) d_attn[(size_t)row * 8 + f] = e[f] * inv;
    }
}

// last step: no attention, no c store; hl written fp32 for k_final
__global__ void __launch_bounds__(256) k_lstm_last() {
    int row = blockIdx.x * 8 + (threadIdx.x >> 5);
    int lane = threadIdx.x & 31;
    int j0 = lane * 4;
    const __half* gr = d_gates + (size_t)row * GW;
    uint2 ri = *(const uint2*)(gr + j0);
    uint2 rf = *(const uint2*)(gr + 128 + j0);
    uint2 rg = *(const uint2*)(gr + 256 + j0);
    uint2 ro = *(const uint2*)(gr + 384 + j0);
    float2 i01 = __half22float2(*(__half2*)&ri.x), i23 = __half22float2(*(__half2*)&ri.y);
    float2 f01 = __half22float2(*(__half2*)&rf.x), f23 = __half22float2(*(__half2*)&rf.y);
    float2 g01 = __half22float2(*(__half2*)&rg.x), g23 = __half22float2(*(__half2*)&rg.y);
    float2 o01 = __half22float2(*(__half2*)&ro.x), o23 = __half22float2(*(__half2*)&ro.y);
    float gi[4] = {i01.x, i01.y, i23.x, i23.y};
    float gf[4] = {f01.x, f01.y, f23.x, f23.y};
    float gg[4] = {g01.x, g01.y, g23.x, g23.y};
    float go[4] = {o01.x, o01.y, o23.x, o23.y};
    float4 co4 = *(const float4*)(d_c + (size_t)row * 128 + j0);
    float co[4] = {co4.x, co4.y, co4.z, co4.w};
    float hl[4];
    #pragma unroll
    for (int k = 0; k < 4; k++) {
        float cn = fmaf(sigf(gf[k]), co[k], sigf(gi[k]) * tanhfast(gg[k]));
        hl[k] = sigf(go[k]) * tanhfast(cn);
    }
    *(float4*)(d_hl + (size_t)row * 128 + j0) = make_float4(hl[0], hl[1], hl[2], hl[3]);
}

// ---------------- final: out[b] = mean(hq[2b], hq[2b+1]) . mean_support ----------------
__global__ void k_final(float* __restrict__ out) {
    __shared__ float ms[128];
    int t = threadIdx.x;
    if (t < 128) ms[t] = d_MS[t];
    __syncthreads();
    int b = blockIdx.x * 8 + (t >> 5);
    int lane = t & 31;
    const float* q0 = d_q  + (size_t)b * 256;
    const float* h0 = d_hl + (size_t)b * 256;
    int j = lane * 4;
    float4 qa = *(const float4*)(q0 + j);
    float4 qb = *(const float4*)(q0 + 128 + j);
    float4 ha = *(const float4*)(h0 + j);
    float4 hb = *(const float4*)(h0 + 128 + j);
    float4 m4 = *(const float4*)(ms + j);
    float p = 0.5f * ((qa.x + ha.x + qb.x + hb.x) * m4.x +
                      (qa.y + ha.y + qb.y + hb.y) * m4.y +
                      (qa.z + ha.z + qb.z + hb.z) * m4.z +
                      (qa.w + ha.w + qb.w + hb.w) * m4.w);
    #pragma unroll
    for (int o = 16; o; o >>= 1) p += __shfl_xor_sync(0xffffffffu, p, o);
    if (lane == 0) out[b] = p;
}

// ---------------- launcher ----------------
extern "C" void kernel_launch(void* const* d_in, const int* in_sizes, int n_in,
                              void* d_out, int out_size) {
    const int*   qp  = (const int*)d_in[0];
    const int*   sp  = (const int*)d_in[1];
    const float* emb = (const float*)d_in[2];
    const float* gW  = (const float*)d_in[3];
    const float* gb  = (const float*)d_in[4];
    const float* p1W = (const float*)d_in[5];
    const float* p1b = (const float*)d_in[6];
    const float* p2W = (const float*)d_in[7];
    const float* p2b = (const float*)d_in[8];
    const float* lng = (const float*)d_in[9];
    const float* lnb = (const float*)d_in[10];
    const float* Wih = (const float*)d_in[11];
    const float* Whh = (const float*)d_in[12];
    const float* bih = (const float*)d_in[13];
    const float* bhh = (const float*)d_in[14];
    float* out = (float*)d_out;

    static int attr_set = 0;
    if (!attr_set) {
        cudaFuncSetAttribute(k_gates, cudaFuncAttributeMaxDynamicSharedMemorySize, SMEM_GATES);
        attr_set = 1;
    }

    k_prep<<<512 + NQ / 8, 256>>>(Wih, Whh, bih, bhh, qp, emb);
    k_support<<<5, 256>>>(sp, emb, gW, gb, p1W, p1b, p2W, p2b, lng, lnb);
    k_s2mean<<<21, 128>>>(Whh);

    // step 0: gates = q@Wih.T + b  (hl slot holds -q), no attn
    k_gates<<<NQ / 128, 256, SMEM_GATES>>>(0);
    k_lstm<<<NQ / 8, 256>>>(1);

    // steps 1,2: gates = q@Wc.T + hl@W1.T + b + attn@S2
    k_gates<<<NQ / 128, 256, SMEM_GATES>>>(1);
    k_lstm<<<NQ / 8, 256>>>(0);
    k_gates<<<NQ / 128, 256, SMEM_GATES>>>(1);
    k_lstm<<<NQ / 8, 256>>>(0);

    // step 3 (last)
    k_gates<<<NQ / 128, 256, SMEM_GATES>>>(1);
    k_lstm_last<<<NQ / 8, 256>>>();

    k_final<<<16384 / 8, 256>>>(out);
}